// round 12
// baseline (speedup 1.0000x reference)
#include <cuda_runtime.h>
#include <cuda_fp16.h>
#include <math.h>
#include <stdint.h>

// ---------------- problem constants ----------------
#define B_SZ   64
#define C_DIM  1536
#define N_TOK  256
#define HIDD   512
#define L_DIM  128
#define G_DIM  256
#define M_CL   64
#define OUT_PER_B (G_DIM + L_DIM * M_CL)   // 8448

#define NEG_LOG320 (-5.768320995793772f)
#define LOGA_LAST  (-0.510825623765991f)
#define A_ROW      (1.0f / 320.0f)   // exp(NEG_LOG320)
#define A_DUST     0.6f              // exp(LOGA_LAST) = 192/320
#define B_COL      (1.0f / 320.0f)

// blocked tile: 128 rows x 40 halves (32 data + 8 pad) = 5120 halves = 10240 B
#define BLK_H   5120
#define BLK_B   10240

// ---------------- scratch (blocked, pre-padded layouts) ----------------
__device__ __half g_xb  [B_SZ * 2 * 48 * BLK_H];  // x^T blocked
__device__ __half g_hb  [B_SZ * 2 * 32 * BLK_H];  // hidden blocked
__device__ __half g_w1b [8 * 48 * BLK_H];         // [Wc1;Ws1] blocked
__device__ __half g_w2b [2 * 16 * BLK_H];         // [Wc2;Ws2pad] blocked
__device__ __half g_wt1b[4 * 48 * BLK_H];         // Wt1 blocked
__device__ __half g_wt2b[2 * 16 * BLK_H];         // Wt2 blocked
__device__ __half g_tb  [48 * BLK_H];             // tokens t blocked (rows 64-127 zero)
__device__ __half g_thb [16 * BLK_H];             // token hidden blocked
__device__ float  g_tg[B_SZ * G_DIM];             // token logits [tok][256]
__device__ float  g_f[B_SZ * L_DIM * N_TOK];
__device__ float  g_s[B_SZ * M_CL * N_TOK];

// ---------------- helpers ----------------
__device__ __forceinline__ void ldsm_x4(uint32_t& r0, uint32_t& r1, uint32_t& r2, uint32_t& r3,
                                        uint32_t addr) {
    asm volatile("ldmatrix.sync.aligned.m8n8.x4.shared.b16 {%0,%1,%2,%3}, [%4];"
        : "=r"(r0), "=r"(r1), "=r"(r2), "=r"(r3) : "r"(addr));
}

__device__ __forceinline__ void mma_f16(float* d, const uint32_t* a, const uint32_t* b) {
    asm volatile(
        "mma.sync.aligned.m16n8k16.row.col.f32.f16.f16.f32 "
        "{%0,%1,%2,%3}, {%4,%5,%6,%7}, {%8,%9}, {%0,%1,%2,%3};"
        : "+f"(d[0]), "+f"(d[1]), "+f"(d[2]), "+f"(d[3])
        : "r"(a[0]), "r"(a[1]), "r"(a[2]), "r"(a[3]), "r"(b[0]), "r"(b[1]));
}

#define MBAR_INIT(mbar, cnt) \
    asm volatile("mbarrier.init.shared.b64 [%0], %1;" :: "r"(mbar), "r"((uint32_t)(cnt)) : "memory")
#define MBAR_EXPECT_TX(mbar, bytes) \
    asm volatile("mbarrier.arrive.expect_tx.shared.b64 _, [%0], %1;" \
                 :: "r"(mbar), "r"((uint32_t)(bytes)) : "memory")
#define BULK_G2S(dst_smem, gsrc, bytes, mbar) \
    asm volatile("cp.async.bulk.shared::cta.global.mbarrier::complete_tx::bytes [%0], [%1], %2, [%3];" \
                 :: "r"(dst_smem), "l"(gsrc), "r"((uint32_t)(bytes)), "r"(mbar) : "memory")

__device__ __forceinline__ void mbar_wait(uint32_t mbar, uint32_t parity) {
    asm volatile(
        "{\n\t.reg .pred P1;\n\t"
        "WAIT_LOOP_%=:\n\t"
        "mbarrier.try_wait.parity.acquire.cta.shared::cta.b64 P1, [%0], %1, 0x989680;\n\t"
        "@P1 bra.uni WAIT_DONE_%=;\n\t"
        "bra.uni WAIT_LOOP_%=;\n\t"
        "WAIT_DONE_%=:\n\t}"
        :: "r"(mbar), "r"(parity) : "memory");
}

#define HTS       40
#define NS        4
#define STG_BYTES (2 * BLK_B)               // 20480
#define GEMM_SMEM (1024 + NS * STG_BYTES)   // 82944 B

// ==========================================================================
// Merged prepass
// ==========================================================================
#define XT_BLOCKS (48 * 8 * B_SZ)   // 24576
#define PW_BLOCKS 512

__global__ __launch_bounds__(256) void p_prep(
    const float* __restrict__ x,
    const float* __restrict__ Wc1, const float* __restrict__ Ws1,
    const float* __restrict__ Wc2, const float* __restrict__ Ws2,
    const float* __restrict__ Wt1, const float* __restrict__ Wt2,
    const float* __restrict__ t)
{
    __shared__ float sm[32][33];
    const int blk = blockIdx.x;
    const int tid = threadIdx.x;

    if (blk < XT_BLOCKS) {
        const int b   = blk / 384;
        const int rem = blk - b * 384;
        const int ct  = (rem >> 3) * 32;
        const int nt  = (rem & 7) * 32;
        const int tx = tid & 31;
        const int ty = tid >> 5;

#pragma unroll
        for (int i = 0; i < 4; i++) {
            int c = ct + ty + i * 8;
            sm[ty + i * 8][tx] = x[((size_t)b * C_DIM + c) * N_TOK + nt + tx];
        }
        __syncthreads();
        const int kt = ct >> 5;
#pragma unroll
        for (int i = 0; i < 4; i++) {
            int n = nt + ty + i * 8;
            size_t dst = (size_t)(((b * 2) + (n >> 7)) * 48 + kt) * BLK_H
                       + (n & 127) * HTS + tx;
            g_xb[dst] = __float2half_rn(sm[tx][ty + i * 8]);
        }
    } else {
        const int n1 = 1024 * C_DIM;
        const int n2 = 256 * HIDD;
        const int n3 = 512 * C_DIM;
        const int n4 = 256 * HIDD;
        const int n5 = B_SZ * C_DIM;
        const int total = n1 + n2 + n3 + n4 + n5;
        const int wb = blk - XT_BLOCKS;
        for (int idx = wb * 256 + tid; idx < total; idx += PW_BLOCKS * 256) {
            if (idx < n1) {
                int o = idx / C_DIM, k = idx - o * C_DIM;
                float v = (o < 512) ? Wc1[idx] : Ws1[idx - 512 * C_DIM];
                g_w1b[(size_t)((o >> 7) * 48 + (k >> 5)) * BLK_H + (o & 127) * HTS + (k & 31)]
                    = __float2half_rn(v);
            } else if (idx < n1 + n2) {
                int j = idx - n1;
                int o = j >> 9, k = j & 511;
                float v = (o < 128) ? Wc2[j]
                        : (o < 192) ? Ws2[j - 128 * HIDD] : 0.f;
                g_w2b[(size_t)((o >> 7) * 16 + (k >> 5)) * BLK_H + (o & 127) * HTS + (k & 31)]
                    = __float2half_rn(v);
            } else if (idx < n1 + n2 + n3) {
                int j = idx - n1 - n2;
                int o = j / C_DIM, k = j - o * C_DIM;
                g_wt1b[(size_t)((o >> 7) * 48 + (k >> 5)) * BLK_H + (o & 127) * HTS + (k & 31)]
                    = __float2half_rn(Wt1[j]);
            } else if (idx < n1 + n2 + n3 + n4) {
                int j = idx - n1 - n2 - n3;
                int o = j >> 9, k = j & 511;
                g_wt2b[(size_t)((o >> 7) * 16 + (k >> 5)) * BLK_H + (o & 127) * HTS + (k & 31)]
                    = __float2half_rn(Wt2[j]);
            } else {
                int j = idx - n1 - n2 - n3 - n4;
                int r = j / C_DIM, k = j - r * C_DIM;
                g_tb[(size_t)(k >> 5) * BLK_H + r * HTS + (k & 31)] = __float2half_rn(t[j]);
            }
        }
    }
}

// ==========================================================================
// Kernel 1: h = relu(x^T W1^T + b1) (mt 0..7) + token layer1 (mt==8)
// ==========================================================================
__global__ __launch_bounds__(256, 2) void k1_mma(
    const float* __restrict__ bc1, const float* __restrict__ bs1,
    const float* __restrict__ bt1)
{
    const int b  = blockIdx.z;
    const int mt = blockIdx.y;
    const int nt = blockIdx.x;

    const bool token = (mt == 8);
    if (token && (nt != 0 || b >= 4)) return;

    extern __shared__ __half smh[];
    const uint32_t sbase = (uint32_t)__cvta_generic_to_shared(smh);
    const uint32_t mb    = sbase;
    const uint32_t st0   = sbase + 1024;

    const __half* Asrc;
    const __half* Bsrc;
    const float*  bias;
    __half*       Odst;
    if (token) {
        Asrc = g_tb;
        Bsrc = g_wt1b + (size_t)(b * 48) * BLK_H;
        bias = bt1 + b * 128;
        Odst = g_thb + (size_t)(b * 4) * BLK_H;
    } else {
        Asrc = g_xb  + (size_t)((b * 2 + nt) * 48) * BLK_H;
        Bsrc = g_w1b + (size_t)(mt * 48) * BLK_H;
        bias = (mt < 4) ? (bc1 + mt * 128) : (bs1 + (mt - 4) * 128);
        Odst = g_hb + (size_t)((b * 2 + nt) * 32 + mt * 4) * BLK_H;
    }

    const int tid  = threadIdx.x;
    const int warp = tid >> 5, lane = tid & 31;
    const int g = lane >> 2, t = lane & 3;
    const int wm = warp >> 2, wn = warp & 3;

    const int lrow = lane & 15;
    const int lcol = (lane >> 4) * 8;

    const uint32_t a_base = st0 + (uint32_t)((wm * 64 + lrow) * HTS + lcol) * 2u;
    const uint32_t b_base = st0 + BLK_B + (uint32_t)((wn * 32 + lrow) * HTS + lcol) * 2u;

    if (tid == 0) {
#pragma unroll
        for (int s = 0; s < NS; s++) MBAR_INIT(mb + 8 * s, 1);
    }
    __syncthreads();
    if (tid == 0) {
#pragma unroll
        for (int s = 0; s < NS; s++) {
            MBAR_EXPECT_TX(mb + 8 * s, STG_BYTES);
            BULK_G2S(st0 + s * STG_BYTES,         Asrc + (size_t)s * BLK_H, BLK_B, mb + 8 * s);
            BULK_G2S(st0 + s * STG_BYTES + BLK_B, Bsrc + (size_t)s * BLK_H, BLK_B, mb + 8 * s);
        }
    }

    float acc[4][4][4];
#pragma unroll
    for (int i = 0; i < 4; i++)
#pragma unroll
        for (int j = 0; j < 4; j++)
#pragma unroll
            for (int q = 0; q < 4; q++) acc[i][j][q] = 0.f;

    const int KT = C_DIM / 32;   // 48
    for (int kt = 0; kt < KT; kt++) {
        const int s = kt & (NS - 1);
        const uint32_t parity = (kt >> 2) & 1;
        mbar_wait(mb + 8 * s, parity);

        const uint32_t abuf = a_base + s * STG_BYTES;
        const uint32_t bbuf = b_base + s * STG_BYTES;

#pragma unroll
        for (int kk = 0; kk < 2; kk++) {
            uint32_t af[4][4];
#pragma unroll
            for (int mi = 0; mi < 4; mi++)
                ldsm_x4(af[mi][0], af[mi][1], af[mi][2], af[mi][3],
                        abuf + mi * (16 * HTS * 2) + kk * 32);
            uint32_t bf[4][2];
#pragma unroll
            for (int nip = 0; nip < 2; nip++) {
                uint32_t r0, r1, r2, r3;
                ldsm_x4(r0, r1, r2, r3, bbuf + nip * (16 * HTS * 2) + kk * 32);
                bf[2 * nip + 0][0] = r0; bf[2 * nip + 0][1] = r2;
                bf[2 * nip + 1][0] = r1; bf[2 * nip + 1][1] = r3;
            }
#pragma unroll
            for (int mi = 0; mi < 4; mi++)
#pragma unroll
                for (int ni = 0; ni < 4; ni++)
                    mma_f16(acc[mi][ni], af[mi], bf[ni]);
        }
        __syncthreads();
        if (tid == 0 && kt + NS < KT) {
            const int kn = kt + NS;
            MBAR_EXPECT_TX(mb + 8 * s, STG_BYTES);
            BULK_G2S(st0 + s * STG_BYTES,         Asrc + (size_t)kn * BLK_H, BLK_B, mb + 8 * s);
            BULK_G2S(st0 + s * STG_BYTES + BLK_B, Bsrc + (size_t)kn * BLK_H, BLK_B, mb + 8 * s);
        }
    }

    float bvv[4][2];
#pragma unroll
    for (int ni = 0; ni < 4; ni++) {
        int col = wn * 32 + ni * 8 + t * 2;
        bvv[ni][0] = __ldg(bias + col);
        bvv[ni][1] = __ldg(bias + col + 1);
    }
    __half* Ob = Odst + (size_t)wn * BLK_H;
#pragma unroll
    for (int mi = 0; mi < 4; mi++) {
#pragma unroll
        for (int q2 = 0; q2 < 2; q2++) {
            int row = wm * 64 + mi * 16 + q2 * 8 + g;
#pragma unroll
            for (int ni = 0; ni < 4; ni++) {
                int c = ni * 8 + t * 2;
                __half2 hv = __floats2half2_rn(
                    fmaxf(acc[mi][ni][q2 * 2 + 0] + bvv[ni][0], 0.f),
                    fmaxf(acc[mi][ni][q2 * 2 + 1] + bvv[ni][1], 0.f));
                *(__half2*)(Ob + row * HTS + c) = hv;
            }
        }
    }
}

// ==========================================================================
// Kernel 2: f/s second layers (mt 0..1) + token layer2 (mt==2)
// ==========================================================================
__global__ __launch_bounds__(256, 2) void k2_mma(
    const float* __restrict__ bc2, const float* __restrict__ bs2,
    const float* __restrict__ bt2)
{
    const int b  = blockIdx.z;
    const int mt = blockIdx.y;
    const int nt = blockIdx.x;

    const bool token = (mt == 2);
    if (token && (nt != 0 || b >= 2)) return;

    extern __shared__ __half smh[];
    const uint32_t sbase = (uint32_t)__cvta_generic_to_shared(smh);
    const uint32_t mb    = sbase;
    const uint32_t st0   = sbase + 1024;

    const __half* Asrc;
    const __half* Bsrc;
    if (token) {
        Asrc = g_wt2b + (size_t)(b * 16) * BLK_H;
        Bsrc = g_thb;
    } else {
        Asrc = g_w2b + (size_t)(mt * 16) * BLK_H;
        Bsrc = g_hb  + (size_t)((b * 2 + nt) * 32 + mt * 16) * BLK_H;
    }

    const int tid  = threadIdx.x;
    const int warp = tid >> 5, lane = tid & 31;
    const int g = lane >> 2, t = lane & 3;
    const int wm = warp >> 2, wn = warp & 3;

    const int lrow = lane & 15;
    const int lcol = (lane >> 4) * 8;

    const uint32_t a_base = st0 + (uint32_t)((wm * 64 + lrow) * HTS + lcol) * 2u;
    const uint32_t b_base = st0 + BLK_B + (uint32_t)((wn * 32 + lrow) * HTS + lcol) * 2u;

    if (tid == 0) {
#pragma unroll
        for (int s = 0; s < NS; s++) MBAR_INIT(mb + 8 * s, 1);
    }
    __syncthreads();
    if (tid == 0) {
#pragma unroll
        for (int s = 0; s < NS; s++) {
            MBAR_EXPECT_TX(mb + 8 * s, STG_BYTES);
            BULK_G2S(st0 + s * STG_BYTES,         Asrc + (size_t)s * BLK_H, BLK_B, mb + 8 * s);
            BULK_G2S(st0 + s * STG_BYTES + BLK_B, Bsrc + (size_t)s * BLK_H, BLK_B, mb + 8 * s);
        }
    }

    float acc[4][4][4];
#pragma unroll
    for (int i = 0; i < 4; i++)
#pragma unroll
        for (int j = 0; j < 4; j++)
#pragma unroll
            for (int q = 0; q < 4; q++) acc[i][j][q] = 0.f;

    const int KT = HIDD / 32;   // 16
    for (int kt = 0; kt < KT; kt++) {
        const int s = kt & (NS - 1);
        const uint32_t parity = (kt >> 2) & 1;
        mbar_wait(mb + 8 * s, parity);

        const uint32_t abuf = a_base + s * STG_BYTES;
        const uint32_t bbuf = b_base + s * STG_BYTES;

#pragma unroll
        for (int kk = 0; kk < 2; kk++) {
            uint32_t af[4][4];
#pragma unroll
            for (int mi = 0; mi < 4; mi++)
                ldsm_x4(af[mi][0], af[mi][1], af[mi][2], af[mi][3],
                        abuf + mi * (16 * HTS * 2) + kk * 32);
            uint32_t bf[4][2];
#pragma unroll
            for (int nip = 0; nip < 2; nip++) {
                uint32_t r0, r1, r2, r3;
                ldsm_x4(r0, r1, r2, r3, bbuf + nip * (16 * HTS * 2) + kk * 32);
                bf[2 * nip + 0][0] = r0; bf[2 * nip + 0][1] = r2;
                bf[2 * nip + 1][0] = r1; bf[2 * nip + 1][1] = r3;
            }
#pragma unroll
            for (int mi = 0; mi < 4; mi++)
#pragma unroll
                for (int ni = 0; ni < 4; ni++)
                    mma_f16(acc[mi][ni], af[mi], bf[ni]);
        }
        __syncthreads();
        if (tid == 0 && kt + NS < KT) {
            const int kn = kt + NS;
            MBAR_EXPECT_TX(mb + 8 * s, STG_BYTES);
            BULK_G2S(st0 + s * STG_BYTES,         Asrc + (size_t)kn * BLK_H, BLK_B, mb + 8 * s);
            BULK_G2S(st0 + s * STG_BYTES + BLK_B, Bsrc + (size_t)kn * BLK_H, BLK_B, mb + 8 * s);
        }
    }

#pragma unroll
    for (int mi = 0; mi < 4; mi++) {
#pragma unroll
        for (int q2 = 0; q2 < 2; q2++) {
            int row = wm * 64 + mi * 16 + q2 * 8 + g;
            if (token) {
                float bv = __ldg(bt2 + b * 128 + row);
#pragma unroll
                for (int ni = 0; ni < 4; ni++) {
                    int col = wn * 32 + ni * 8 + t * 2;
                    if (col < 64) {
                        g_tg[(size_t)col * G_DIM + b * 128 + row]       = acc[mi][ni][q2 * 2 + 0] + bv;
                        g_tg[(size_t)(col + 1) * G_DIM + b * 128 + row] = acc[mi][ni][q2 * 2 + 1] + bv;
                    }
                }
            } else if (mt == 0) {
                float bv = __ldg(bc2 + row);
#pragma unroll
                for (int ni = 0; ni < 4; ni++) {
                    int col = nt * 128 + wn * 32 + ni * 8 + t * 2;
                    float2 v;
                    v.x = acc[mi][ni][q2 * 2 + 0] + bv;
                    v.y = acc[mi][ni][q2 * 2 + 1] + bv;
                    *(float2*)(g_f + ((size_t)b * L_DIM + row) * N_TOK + col) = v;
                }
            } else if (row < 64) {
                float bv = __ldg(bs2 + row);
#pragma unroll
                for (int ni = 0; ni < 4; ni++) {
                    int col = nt * 128 + wn * 32 + ni * 8 + t * 2;
                    float2 v;
                    v.x = acc[mi][ni][q2 * 2 + 0] + bv;
                    v.y = acc[mi][ni][q2 * 2 + 1] + bv;
                    *(float2*)(g_s + ((size_t)b * M_CL + row) * N_TOK + col) = v;
                }
            }
        }
    }
}

// ==========================================================================
// Fused tail v2 (512 threads): LINEAR-domain Sinkhorn (one exp pass) + VLAD
// + intra-norm + token-norm + final norm. P never leaves smem.
// Row-shift invariance: E = exp(Ms - rowmax); scalings u' absorb the shift;
// P = E*u*v*320 identical to log-domain result after the same 3 iterations.
// ==========================================================================
#define PS_LD 260
#define TAIL_THREADS 512
#define TAIL_SMEM ((65 * 256 + 72 + 256 + 64 * PS_LD + 128 * 64 + 64 + 16) * 4)

__global__ __launch_bounds__(TAIL_THREADS) void k_tail(const float* __restrict__ dustp,
                                                       float* __restrict__ out)
{
    extern __shared__ float sh[];
    float* E   = sh;                       // 65*256 (scores -> exp'd kernel)
    float* eu  = E + 65 * 256;             // 72
    float* ev  = eu + 72;                  // 256
    float* ps  = ev + 256;                 // 64*PS_LD
    float* vs  = ps + 64 * PS_LD;          // 128*64
    float* inv = vs + 128 * 64;            // 64
    float* red = inv + 64;                 // 16

    const int b    = blockIdx.x;
    const int tid  = threadIdx.x;
    const int w    = tid >> 5;             // 0..15
    const int lane = tid & 31;
    const float dust = *dustp;
    const float* S = g_s + (size_t)b * M_CL * N_TOK;

    // load scores + dust row
    for (int i = tid; i < 64 * 256; i += TAIL_THREADS) E[i] = S[i];
    if (tid < 256) { E[64 * 256 + tid] = dust; ev[tid] = 1.f; }
    __syncthreads();

    // rowmax + exponentiate in place (the ONLY exp pass): warp per row
    for (int r = w; r < 65; r += 16) {
        float vals[8];
        float mx = -INFINITY;
#pragma unroll
        for (int q = 0; q < 8; q++) {
            vals[q] = E[r * 256 + lane + 32 * q];
            mx = fmaxf(mx, vals[q]);
        }
#pragma unroll
        for (int off = 16; off; off >>= 1)
            mx = fmaxf(mx, __shfl_xor_sync(0xffffffffu, mx, off));
#pragma unroll
        for (int q = 0; q < 8; q++)
            E[r * 256 + lane + 32 * q] = expf(vals[q] - mx);
    }
    __syncthreads();

    // 3 linear Sinkhorn iterations: u then v
    for (int it = 0; it < 3; it++) {
        // u_r = a_r / sum_n E[r][n] * ev[n]   (warp per row)
        for (int r = w; r < 65; r += 16) {
            float s = 0.f;
#pragma unroll
            for (int q = 0; q < 8; q++)
                s += E[r * 256 + lane + 32 * q] * ev[lane + 32 * q];
#pragma unroll
            for (int off = 16; off; off >>= 1)
                s += __shfl_xor_sync(0xffffffffu, s, off);
            if (lane == 0)
                eu[r] = ((r == 64) ? A_DUST : A_ROW) / s;
        }
        __syncthreads();
        // v_n = b_n / sum_m E[m][n] * eu[m]   (thread per column; FMA-only)
        if (tid < 256) {
            float s0 = 0.f, s1 = 0.f, s2 = 0.f, s3 = 0.f;
#pragma unroll
            for (int m = 0; m < 64; m += 4) {
                s0 += E[(m + 0) * 256 + tid] * eu[m + 0];
                s1 += E[(m + 1) * 256 + tid] * eu[m + 1];
                s2 += E[(m + 2) * 256 + tid] * eu[m + 2];
                s3 += E[(m + 3) * 256 + tid] * eu[m + 3];
            }
            float s = (s0 + s1) + (s2 + s3) + E[64 * 256 + tid] * eu[64];
            ev[tid] = B_COL / s;
        }
        __syncthreads();
    }

    // P (drop dustbin) into padded smem: p = E * u * v * 320  (no exp)
    for (int i = tid; i < 64 * 256; i += TAIL_THREADS) {
        int m = i >> 8, n = i & 255;
        ps[m * PS_LD + n] = E[i] * eu[m] * ev[n] * 320.f;
    }
    __syncthreads();

    // ---- VLAD: vlad[l][m] = sum_n f[l][n] * p[m][n]  (512 threads) ----
    const float* F = g_f + (size_t)b * L_DIM * N_TOK;
    const int m  = tid & 63;
    const int lg = tid >> 6;                 // 0..7, each handles 16 l rows
    const float4* pr = (const float4*)(ps + m * PS_LD);

    float acc[16];
#pragma unroll
    for (int i = 0; i < 16; i++) acc[i] = 0.f;

    for (int nc = 0; nc < 64; nc += 4) {
        float4 pv0 = pr[nc + 0], pv1 = pr[nc + 1], pv2 = pr[nc + 2], pv3 = pr[nc + 3];
#pragma unroll
        for (int li = 0; li < 16; li++) {
            const float4* fr = (const float4*)(F + (size_t)(lg * 16 + li) * N_TOK);
            float4 f0 = fr[nc + 0], f1 = fr[nc + 1], f2 = fr[nc + 2], f3 = fr[nc + 3];
            float a = acc[li];
            a += f0.x * pv0.x + f0.y * pv0.y + f0.z * pv0.z + f0.w * pv0.w;
            a += f1.x * pv1.x + f1.y * pv1.y + f1.z * pv1.z + f1.w * pv1.w;
            a += f2.x * pv2.x + f2.y * pv2.y + f2.z * pv2.z + f2.w * pv2.w;
            a += f3.x * pv3.x + f3.y * pv3.y + f3.z * pv3.z + f3.w * pv3.w;
            acc[li] = a;
        }
    }
#pragma unroll
    for (int li = 0; li < 16; li++) vs[(lg * 16 + li) * 64 + m] = acc[li];
    __syncthreads();

    // intra-norm over l per cluster m
    if (tid < 64) {
        float ss = 0.f;
        for (int l = 0; l < 128; l++) {
            float vv = vs[l * 64 + tid];
            ss += vv * vv;
        }
        inv[tid] = 1.f / fmaxf(sqrtf(ss), 1e-12f);
    }
    __syncthreads();

    // ---- token L2 norm (threads 0-255) ----
    float tval = 0.f;
    if (tid < 256) tval = g_tg[(size_t)b * G_DIM + tid];
    float sst = tval * tval;
#pragma unroll
    for (int off = 16; off; off >>= 1) sst += __shfl_xor_sync(0xffffffffu, sst, off);
    if (lane == 0) red[w] = sst;   // warps 8-15 contribute 0
    __syncthreads();
    float ttot = 0.f;
#pragma unroll
    for (int i = 0; i < 8; i++) ttot += red[i];
    float tnorm = tval * (1.f / fmaxf(sqrtf(ttot), 1e-12f));
    __syncthreads();   // red reuse

    // ---- final whole-vector norm ----
    float ssf = (tid < 256) ? tnorm * tnorm : 0.f;
    for (int i = tid; i < L_DIM * M_CL; i += TAIL_THREADS) {
        float vv = vs[i] * inv[i & 63];
        ssf += vv * vv;
    }
#pragma unroll
    for (int off = 16; off; off >>= 1) ssf += __shfl_xor_sync(0xffffffffu, ssf, off);
    if (lane == 0) red[w] = ssf;
    __syncthreads();
    float tot = 0.f;
#pragma unroll
    for (int i = 0; i < 16; i++) tot += red[i];
    float sc = 1.f / fmaxf(sqrtf(tot), 1e-12f);

    // ---- write out ----
    float* O = out + (size_t)b * OUT_PER_B;
    if (tid < 256) O[tid] = tnorm * sc;
    for (int i = tid; i < L_DIM * M_CL; i += TAIL_THREADS)
        O[G_DIM + i] = vs[i] * inv[i & 63] * sc;
}

// ==========================================================================
// launch — 4 kernels
// ==========================================================================
extern "C" void kernel_launch(void* const* d_in, const int* in_sizes, int n_in,
                              void* d_out, int out_size)
{
    (void)in_sizes; (void)n_in; (void)out_size;
    const float* x    = (const float*)d_in[0];
    const float* t    = (const float*)d_in[1];
    const float* Wt1  = (const float*)d_in[2];
    const float* bt1  = (const float*)d_in[3];
    const float* Wt2  = (const float*)d_in[4];
    const float* bt2  = (const float*)d_in[5];
    const float* Wc1  = (const float*)d_in[6];
    const float* bc1  = (const float*)d_in[7];
    const float* Wc2  = (const float*)d_in[8];
    const float* bc2  = (const float*)d_in[9];
    const float* Ws1  = (const float*)d_in[10];
    const float* bs1  = (const float*)d_in[11];
    const float* Ws2  = (const float*)d_in[12];
    const float* bs2  = (const float*)d_in[13];
    const float* dust = (const float*)d_in[14];
    float* out = (float*)d_out;

    cudaFuncSetAttribute(k1_mma, cudaFuncAttributeMaxDynamicSharedMemorySize, GEMM_SMEM);
    cudaFuncSetAttribute(k2_mma, cudaFuncAttributeMaxDynamicSharedMemorySize, GEMM_SMEM);
    cudaFuncSetAttribute(k_tail, cudaFuncAttributeMaxDynamicSharedMemorySize, TAIL_SMEM);

    p_prep<<<XT_BLOCKS + PW_BLOCKS, 256>>>(x, Wc1, Ws1, Wc2, Ws2, Wt1, Wt2, t);  // idx 0
    k1_mma<<<dim3(2, 9, B_SZ), 256, GEMM_SMEM>>>(bc1, bs1, bt1);                  // idx 1
    k2_mma<<<dim3(2, 3, B_SZ), 256, GEMM_SMEM>>>(bc2, bs2, bt2);                  // idx 2
    k_tail<<<B_SZ, TAIL_THREADS, TAIL_SMEM>>>(dust, out);                         // idx 3 (ncu)
}

// round 13
// speedup vs baseline: 1.1473x; 1.1473x over previous
#include <cuda_runtime.h>
#include <cuda_fp16.h>
#include <math.h>
#include <stdint.h>

// ---------------- problem constants ----------------
#define B_SZ   64
#define C_DIM  1536
#define N_TOK  256
#define HIDD   512
#define L_DIM  128
#define G_DIM  256
#define M_CL   64
#define OUT_PER_B (G_DIM + L_DIM * M_CL)   // 8448

#define A_ROW      (1.0f / 320.0f)
#define A_DUST     0.6f              // 192/320
#define B_COL      (1.0f / 320.0f)

// blocked tile: 128 rows x 40 halves (32 data + 8 pad) = 5120 halves = 10240 B
#define BLK_H   5120
#define BLK_B   10240

// ---------------- scratch ----------------
__device__ __half g_xb  [B_SZ * 2 * 48 * BLK_H];
__device__ __half g_hb  [B_SZ * 2 * 32 * BLK_H];
__device__ __half g_w1b [8 * 48 * BLK_H];
__device__ __half g_w2b [2 * 16 * BLK_H];
__device__ __half g_wt1b[4 * 48 * BLK_H];
__device__ __half g_wt2b[2 * 16 * BLK_H];
__device__ __half g_tb  [48 * BLK_H];
__device__ __half g_thb [16 * BLK_H];
__device__ float  g_tg[B_SZ * G_DIM];
__device__ float  g_f[B_SZ * L_DIM * N_TOK];
__device__ float  g_s[B_SZ * M_CL * N_TOK];

// ---------------- helpers ----------------
__device__ __forceinline__ void ldsm_x4(uint32_t& r0, uint32_t& r1, uint32_t& r2, uint32_t& r3,
                                        uint32_t addr) {
    asm volatile("ldmatrix.sync.aligned.m8n8.x4.shared.b16 {%0,%1,%2,%3}, [%4];"
        : "=r"(r0), "=r"(r1), "=r"(r2), "=r"(r3) : "r"(addr));
}

__device__ __forceinline__ void mma_f16(float* d, const uint32_t* a, const uint32_t* b) {
    asm volatile(
        "mma.sync.aligned.m16n8k16.row.col.f32.f16.f16.f32 "
        "{%0,%1,%2,%3}, {%4,%5,%6,%7}, {%8,%9}, {%0,%1,%2,%3};"
        : "+f"(d[0]), "+f"(d[1]), "+f"(d[2]), "+f"(d[3])
        : "r"(a[0]), "r"(a[1]), "r"(a[2]), "r"(a[3]), "r"(b[0]), "r"(b[1]));
}

#define MBAR_INIT(mbar, cnt) \
    asm volatile("mbarrier.init.shared.b64 [%0], %1;" :: "r"(mbar), "r"((uint32_t)(cnt)) : "memory")
#define MBAR_EXPECT_TX(mbar, bytes) \
    asm volatile("mbarrier.arrive.expect_tx.shared.b64 _, [%0], %1;" \
                 :: "r"(mbar), "r"((uint32_t)(bytes)) : "memory")
#define BULK_G2S(dst_smem, gsrc, bytes, mbar) \
    asm volatile("cp.async.bulk.shared::cta.global.mbarrier::complete_tx::bytes [%0], [%1], %2, [%3];" \
                 :: "r"(dst_smem), "l"(gsrc), "r"((uint32_t)(bytes)), "r"(mbar) : "memory")

__device__ __forceinline__ void mbar_wait(uint32_t mbar, uint32_t parity) {
    asm volatile(
        "{\n\t.reg .pred P1;\n\t"
        "WAIT_LOOP_%=:\n\t"
        "mbarrier.try_wait.parity.acquire.cta.shared::cta.b64 P1, [%0], %1, 0x989680;\n\t"
        "@P1 bra.uni WAIT_DONE_%=;\n\t"
        "bra.uni WAIT_LOOP_%=;\n\t"
        "WAIT_DONE_%=:\n\t}"
        :: "r"(mbar), "r"(parity) : "memory");
}

#define HTS       40
#define NS        4
#define STG_BYTES (2 * BLK_B)               // 20480
#define GEMM_SMEM (1024 + NS * STG_BYTES)   // 82944 B

// ==========================================================================
// Merged prepass
// ==========================================================================
#define XT_BLOCKS (48 * 8 * B_SZ)   // 24576
#define PW_BLOCKS 512

__global__ __launch_bounds__(256) void p_prep(
    const float* __restrict__ x,
    const float* __restrict__ Wc1, const float* __restrict__ Ws1,
    const float* __restrict__ Wc2, const float* __restrict__ Ws2,
    const float* __restrict__ Wt1, const float* __restrict__ Wt2,
    const float* __restrict__ t)
{
    __shared__ float sm[32][33];
    const int blk = blockIdx.x;
    const int tid = threadIdx.x;

    if (blk < XT_BLOCKS) {
        const int b   = blk / 384;
        const int rem = blk - b * 384;
        const int ct  = (rem >> 3) * 32;
        const int nt  = (rem & 7) * 32;
        const int tx = tid & 31;
        const int ty = tid >> 5;

#pragma unroll
        for (int i = 0; i < 4; i++) {
            int c = ct + ty + i * 8;
            sm[ty + i * 8][tx] = x[((size_t)b * C_DIM + c) * N_TOK + nt + tx];
        }
        __syncthreads();
        const int kt = ct >> 5;
#pragma unroll
        for (int i = 0; i < 4; i++) {
            int n = nt + ty + i * 8;
            size_t dst = (size_t)(((b * 2) + (n >> 7)) * 48 + kt) * BLK_H
                       + (n & 127) * HTS + tx;
            g_xb[dst] = __float2half_rn(sm[tx][ty + i * 8]);
        }
    } else {
        const int n1 = 1024 * C_DIM;
        const int n2 = 256 * HIDD;
        const int n3 = 512 * C_DIM;
        const int n4 = 256 * HIDD;
        const int n5 = B_SZ * C_DIM;
        const int total = n1 + n2 + n3 + n4 + n5;
        const int wb = blk - XT_BLOCKS;
        for (int idx = wb * 256 + tid; idx < total; idx += PW_BLOCKS * 256) {
            if (idx < n1) {
                int o = idx / C_DIM, k = idx - o * C_DIM;
                float v = (o < 512) ? Wc1[idx] : Ws1[idx - 512 * C_DIM];
                g_w1b[(size_t)((o >> 7) * 48 + (k >> 5)) * BLK_H + (o & 127) * HTS + (k & 31)]
                    = __float2half_rn(v);
            } else if (idx < n1 + n2) {
                int j = idx - n1;
                int o = j >> 9, k = j & 511;
                float v = (o < 128) ? Wc2[j]
                        : (o < 192) ? Ws2[j - 128 * HIDD] : 0.f;
                g_w2b[(size_t)((o >> 7) * 16 + (k >> 5)) * BLK_H + (o & 127) * HTS + (k & 31)]
                    = __float2half_rn(v);
            } else if (idx < n1 + n2 + n3) {
                int j = idx - n1 - n2;
                int o = j / C_DIM, k = j - o * C_DIM;
                g_wt1b[(size_t)((o >> 7) * 48 + (k >> 5)) * BLK_H + (o & 127) * HTS + (k & 31)]
                    = __float2half_rn(Wt1[j]);
            } else if (idx < n1 + n2 + n3 + n4) {
                int j = idx - n1 - n2 - n3;
                int o = j >> 9, k = j & 511;
                g_wt2b[(size_t)((o >> 7) * 16 + (k >> 5)) * BLK_H + (o & 127) * HTS + (k & 31)]
                    = __float2half_rn(Wt2[j]);
            } else {
                int j = idx - n1 - n2 - n3 - n4;
                int r = j / C_DIM, k = j - r * C_DIM;
                g_tb[(size_t)(k >> 5) * BLK_H + r * HTS + (k & 31)] = __float2half_rn(t[j]);
            }
        }
    }
}

// ==========================================================================
// Kernel 1: h = relu(x^T W1^T + b1) (mt 0..7) + token layer1 (mt==8)
// ==========================================================================
__global__ __launch_bounds__(256, 2) void k1_mma(
    const float* __restrict__ bc1, const float* __restrict__ bs1,
    const float* __restrict__ bt1)
{
    const int b  = blockIdx.z;
    const int mt = blockIdx.y;
    const int nt = blockIdx.x;

    const bool token = (mt == 8);
    if (token && (nt != 0 || b >= 4)) return;

    extern __shared__ __half smh[];
    const uint32_t sbase = (uint32_t)__cvta_generic_to_shared(smh);
    const uint32_t mb    = sbase;
    const uint32_t st0   = sbase + 1024;

    const __half* Asrc;
    const __half* Bsrc;
    const float*  bias;
    __half*       Odst;
    if (token) {
        Asrc = g_tb;
        Bsrc = g_wt1b + (size_t)(b * 48) * BLK_H;
        bias = bt1 + b * 128;
        Odst = g_thb + (size_t)(b * 4) * BLK_H;
    } else {
        Asrc = g_xb  + (size_t)((b * 2 + nt) * 48) * BLK_H;
        Bsrc = g_w1b + (size_t)(mt * 48) * BLK_H;
        bias = (mt < 4) ? (bc1 + mt * 128) : (bs1 + (mt - 4) * 128);
        Odst = g_hb + (size_t)((b * 2 + nt) * 32 + mt * 4) * BLK_H;
    }

    const int tid  = threadIdx.x;
    const int warp = tid >> 5, lane = tid & 31;
    const int g = lane >> 2, t = lane & 3;
    const int wm = warp >> 2, wn = warp & 3;

    const int lrow = lane & 15;
    const int lcol = (lane >> 4) * 8;

    const uint32_t a_base = st0 + (uint32_t)((wm * 64 + lrow) * HTS + lcol) * 2u;
    const uint32_t b_base = st0 + BLK_B + (uint32_t)((wn * 32 + lrow) * HTS + lcol) * 2u;

    if (tid == 0) {
#pragma unroll
        for (int s = 0; s < NS; s++) MBAR_INIT(mb + 8 * s, 1);
    }
    __syncthreads();
    if (tid == 0) {
#pragma unroll
        for (int s = 0; s < NS; s++) {
            MBAR_EXPECT_TX(mb + 8 * s, STG_BYTES);
            BULK_G2S(st0 + s * STG_BYTES,         Asrc + (size_t)s * BLK_H, BLK_B, mb + 8 * s);
            BULK_G2S(st0 + s * STG_BYTES + BLK_B, Bsrc + (size_t)s * BLK_H, BLK_B, mb + 8 * s);
        }
    }

    float acc[4][4][4];
#pragma unroll
    for (int i = 0; i < 4; i++)
#pragma unroll
        for (int j = 0; j < 4; j++)
#pragma unroll
            for (int q = 0; q < 4; q++) acc[i][j][q] = 0.f;

    const int KT = C_DIM / 32;   // 48
    for (int kt = 0; kt < KT; kt++) {
        const int s = kt & (NS - 1);
        const uint32_t parity = (kt >> 2) & 1;
        mbar_wait(mb + 8 * s, parity);

        const uint32_t abuf = a_base + s * STG_BYTES;
        const uint32_t bbuf = b_base + s * STG_BYTES;

#pragma unroll
        for (int kk = 0; kk < 2; kk++) {
            uint32_t af[4][4];
#pragma unroll
            for (int mi = 0; mi < 4; mi++)
                ldsm_x4(af[mi][0], af[mi][1], af[mi][2], af[mi][3],
                        abuf + mi * (16 * HTS * 2) + kk * 32);
            uint32_t bf[4][2];
#pragma unroll
            for (int nip = 0; nip < 2; nip++) {
                uint32_t r0, r1, r2, r3;
                ldsm_x4(r0, r1, r2, r3, bbuf + nip * (16 * HTS * 2) + kk * 32);
                bf[2 * nip + 0][0] = r0; bf[2 * nip + 0][1] = r2;
                bf[2 * nip + 1][0] = r1; bf[2 * nip + 1][1] = r3;
            }
#pragma unroll
            for (int mi = 0; mi < 4; mi++)
#pragma unroll
                for (int ni = 0; ni < 4; ni++)
                    mma_f16(acc[mi][ni], af[mi], bf[ni]);
        }
        __syncthreads();
        if (tid == 0 && kt + NS < KT) {
            const int kn = kt + NS;
            MBAR_EXPECT_TX(mb + 8 * s, STG_BYTES);
            BULK_G2S(st0 + s * STG_BYTES,         Asrc + (size_t)kn * BLK_H, BLK_B, mb + 8 * s);
            BULK_G2S(st0 + s * STG_BYTES + BLK_B, Bsrc + (size_t)kn * BLK_H, BLK_B, mb + 8 * s);
        }
    }

    float bvv[4][2];
#pragma unroll
    for (int ni = 0; ni < 4; ni++) {
        int col = wn * 32 + ni * 8 + t * 2;
        bvv[ni][0] = __ldg(bias + col);
        bvv[ni][1] = __ldg(bias + col + 1);
    }
    __half* Ob = Odst + (size_t)wn * BLK_H;
#pragma unroll
    for (int mi = 0; mi < 4; mi++) {
#pragma unroll
        for (int q2 = 0; q2 < 2; q2++) {
            int row = wm * 64 + mi * 16 + q2 * 8 + g;
#pragma unroll
            for (int ni = 0; ni < 4; ni++) {
                int c = ni * 8 + t * 2;
                __half2 hv = __floats2half2_rn(
                    fmaxf(acc[mi][ni][q2 * 2 + 0] + bvv[ni][0], 0.f),
                    fmaxf(acc[mi][ni][q2 * 2 + 1] + bvv[ni][1], 0.f));
                *(__half2*)(Ob + row * HTS + c) = hv;
            }
        }
    }
}

// ==========================================================================
// Kernel 2: f/s second layers (mt 0..1) + token layer2 (mt==2)
// ==========================================================================
__global__ __launch_bounds__(256, 2) void k2_mma(
    const float* __restrict__ bc2, const float* __restrict__ bs2,
    const float* __restrict__ bt2)
{
    const int b  = blockIdx.z;
    const int mt = blockIdx.y;
    const int nt = blockIdx.x;

    const bool token = (mt == 2);
    if (token && (nt != 0 || b >= 2)) return;

    extern __shared__ __half smh[];
    const uint32_t sbase = (uint32_t)__cvta_generic_to_shared(smh);
    const uint32_t mb    = sbase;
    const uint32_t st0   = sbase + 1024;

    const __half* Asrc;
    const __half* Bsrc;
    if (token) {
        Asrc = g_wt2b + (size_t)(b * 16) * BLK_H;
        Bsrc = g_thb;
    } else {
        Asrc = g_w2b + (size_t)(mt * 16) * BLK_H;
        Bsrc = g_hb  + (size_t)((b * 2 + nt) * 32 + mt * 16) * BLK_H;
    }

    const int tid  = threadIdx.x;
    const int warp = tid >> 5, lane = tid & 31;
    const int g = lane >> 2, t = lane & 3;
    const int wm = warp >> 2, wn = warp & 3;

    const int lrow = lane & 15;
    const int lcol = (lane >> 4) * 8;

    const uint32_t a_base = st0 + (uint32_t)((wm * 64 + lrow) * HTS + lcol) * 2u;
    const uint32_t b_base = st0 + BLK_B + (uint32_t)((wn * 32 + lrow) * HTS + lcol) * 2u;

    if (tid == 0) {
#pragma unroll
        for (int s = 0; s < NS; s++) MBAR_INIT(mb + 8 * s, 1);
    }
    __syncthreads();
    if (tid == 0) {
#pragma unroll
        for (int s = 0; s < NS; s++) {
            MBAR_EXPECT_TX(mb + 8 * s, STG_BYTES);
            BULK_G2S(st0 + s * STG_BYTES,         Asrc + (size_t)s * BLK_H, BLK_B, mb + 8 * s);
            BULK_G2S(st0 + s * STG_BYTES + BLK_B, Bsrc + (size_t)s * BLK_H, BLK_B, mb + 8 * s);
        }
    }

    float acc[4][4][4];
#pragma unroll
    for (int i = 0; i < 4; i++)
#pragma unroll
        for (int j = 0; j < 4; j++)
#pragma unroll
            for (int q = 0; q < 4; q++) acc[i][j][q] = 0.f;

    const int KT = HIDD / 32;   // 16
    for (int kt = 0; kt < KT; kt++) {
        const int s = kt & (NS - 1);
        const uint32_t parity = (kt >> 2) & 1;
        mbar_wait(mb + 8 * s, parity);

        const uint32_t abuf = a_base + s * STG_BYTES;
        const uint32_t bbuf = b_base + s * STG_BYTES;

#pragma unroll
        for (int kk = 0; kk < 2; kk++) {
            uint32_t af[4][4];
#pragma unroll
            for (int mi = 0; mi < 4; mi++)
                ldsm_x4(af[mi][0], af[mi][1], af[mi][2], af[mi][3],
                        abuf + mi * (16 * HTS * 2) + kk * 32);
            uint32_t bf[4][2];
#pragma unroll
            for (int nip = 0; nip < 2; nip++) {
                uint32_t r0, r1, r2, r3;
                ldsm_x4(r0, r1, r2, r3, bbuf + nip * (16 * HTS * 2) + kk * 32);
                bf[2 * nip + 0][0] = r0; bf[2 * nip + 0][1] = r2;
                bf[2 * nip + 1][0] = r1; bf[2 * nip + 1][1] = r3;
            }
#pragma unroll
            for (int mi = 0; mi < 4; mi++)
#pragma unroll
                for (int ni = 0; ni < 4; ni++)
                    mma_f16(acc[mi][ni], af[mi], bf[ni]);
        }
        __syncthreads();
        if (tid == 0 && kt + NS < KT) {
            const int kn = kt + NS;
            MBAR_EXPECT_TX(mb + 8 * s, STG_BYTES);
            BULK_G2S(st0 + s * STG_BYTES,         Asrc + (size_t)kn * BLK_H, BLK_B, mb + 8 * s);
            BULK_G2S(st0 + s * STG_BYTES + BLK_B, Bsrc + (size_t)kn * BLK_H, BLK_B, mb + 8 * s);
        }
    }

#pragma unroll
    for (int mi = 0; mi < 4; mi++) {
#pragma unroll
        for (int q2 = 0; q2 < 2; q2++) {
            int row = wm * 64 + mi * 16 + q2 * 8 + g;
            if (token) {
                float bv = __ldg(bt2 + b * 128 + row);
#pragma unroll
                for (int ni = 0; ni < 4; ni++) {
                    int col = wn * 32 + ni * 8 + t * 2;
                    if (col < 64) {
                        g_tg[(size_t)col * G_DIM + b * 128 + row]       = acc[mi][ni][q2 * 2 + 0] + bv;
                        g_tg[(size_t)(col + 1) * G_DIM + b * 128 + row] = acc[mi][ni][q2 * 2 + 1] + bv;
                    }
                }
            } else if (mt == 0) {
                float bv = __ldg(bc2 + row);
#pragma unroll
                for (int ni = 0; ni < 4; ni++) {
                    int col = nt * 128 + wn * 32 + ni * 8 + t * 2;
                    float2 v;
                    v.x = acc[mi][ni][q2 * 2 + 0] + bv;
                    v.y = acc[mi][ni][q2 * 2 + 1] + bv;
                    *(float2*)(g_f + ((size_t)b * L_DIM + row) * N_TOK + col) = v;
                }
            } else if (row < 64) {
                float bv = __ldg(bs2 + row);
#pragma unroll
                for (int ni = 0; ni < 4; ni++) {
                    int col = nt * 128 + wn * 32 + ni * 8 + t * 2;
                    float2 v;
                    v.x = acc[mi][ni][q2 * 2 + 0] + bv;
                    v.y = acc[mi][ni][q2 * 2 + 1] + bv;
                    *(float2*)(g_s + ((size_t)b * M_CL + row) * N_TOK + col) = v;
                }
            }
        }
    }
}

// ==========================================================================
// Fused tail v3 (512 threads): linear Sinkhorn + smem-staged VLAD + norms.
// After ps is built, the E buffer is dead -> reuse it to stage F (two 64-row
// halves, fp32, coalesced) so the VLAD inner loop reads smem, not L2.
// ==========================================================================
#define PS_LD 260
#define TAIL_THREADS 512
#define TAIL_SMEM ((65 * 256 + 72 + 256 + 64 * PS_LD + 128 * 64 + 64 + 16) * 4)

__global__ __launch_bounds__(TAIL_THREADS) void k_tail(const float* __restrict__ dustp,
                                                       float* __restrict__ out)
{
    extern __shared__ float sh[];
    float* E   = sh;                       // 65*256; reused as F-stage later
    float* eu  = E + 65 * 256;             // 72
    float* ev  = eu + 72;                  // 256
    float* ps  = ev + 256;                 // 64*PS_LD
    float* vs  = ps + 64 * PS_LD;          // 128*64
    float* inv = vs + 128 * 64;            // 64
    float* red = inv + 64;                 // 16

    const int b    = blockIdx.x;
    const int tid  = threadIdx.x;
    const int w    = tid >> 5;             // 0..15
    const int lane = tid & 31;
    const float dust = *dustp;
    const float* S = g_s + (size_t)b * M_CL * N_TOK;

    // load scores + dust row
    for (int i = tid; i < 64 * 256; i += TAIL_THREADS) E[i] = S[i];
    if (tid < 256) { E[64 * 256 + tid] = dust; ev[tid] = 1.f; }
    __syncthreads();

    // rowmax + exponentiate in place (only exp pass)
    for (int r = w; r < 65; r += 16) {
        float vals[8];
        float mx = -INFINITY;
#pragma unroll
        for (int q = 0; q < 8; q++) {
            vals[q] = E[r * 256 + lane + 32 * q];
            mx = fmaxf(mx, vals[q]);
        }
#pragma unroll
        for (int off = 16; off; off >>= 1)
            mx = fmaxf(mx, __shfl_xor_sync(0xffffffffu, mx, off));
#pragma unroll
        for (int q = 0; q < 8; q++)
            E[r * 256 + lane + 32 * q] = expf(vals[q] - mx);
    }
    __syncthreads();

    // 3 linear Sinkhorn iterations
    for (int it = 0; it < 3; it++) {
        for (int r = w; r < 65; r += 16) {
            float s = 0.f;
#pragma unroll
            for (int q = 0; q < 8; q++)
                s += E[r * 256 + lane + 32 * q] * ev[lane + 32 * q];
#pragma unroll
            for (int off = 16; off; off >>= 1)
                s += __shfl_xor_sync(0xffffffffu, s, off);
            if (lane == 0)
                eu[r] = ((r == 64) ? A_DUST : A_ROW) / s;
        }
        __syncthreads();
        if (tid < 256) {
            float s0 = 0.f, s1 = 0.f, s2 = 0.f, s3 = 0.f;
#pragma unroll
            for (int m = 0; m < 64; m += 4) {
                s0 += E[(m + 0) * 256 + tid] * eu[m + 0];
                s1 += E[(m + 1) * 256 + tid] * eu[m + 1];
                s2 += E[(m + 2) * 256 + tid] * eu[m + 2];
                s3 += E[(m + 3) * 256 + tid] * eu[m + 3];
            }
            float s = (s0 + s1) + (s2 + s3) + E[64 * 256 + tid] * eu[64];
            ev[tid] = B_COL / s;
        }
        __syncthreads();
    }

    // P (drop dustbin) into padded smem
    for (int i = tid; i < 64 * 256; i += TAIL_THREADS) {
        int m = i >> 8, n = i & 255;
        ps[m * PS_LD + n] = E[i] * eu[m] * ev[n] * 320.f;
    }
    __syncthreads();   // E is now dead -> reuse as F stage

    // ---- VLAD with F staged in smem (two 64-row halves) ----
    const float* F = g_f + (size_t)b * L_DIM * N_TOK;
    float* fs = E;                         // 64*256 floats per half
    const int m  = tid & 63;
    const int lg = tid >> 6;               // 0..7, 8 rows each per half
    const float4* pr = (const float4*)(ps + m * PS_LD);

    for (int half = 0; half < 2; half++) {
        // stage: 4096 float4, 8 per thread, coalesced
        const float4* Fg = (const float4*)(F + (size_t)half * 64 * N_TOK);
        float4* fs4 = (float4*)fs;
        for (int i = tid; i < 64 * 64; i += TAIL_THREADS)
            fs4[i] = Fg[i];
        __syncthreads();

        float acc[8];
#pragma unroll
        for (int i = 0; i < 8; i++) acc[i] = 0.f;

        for (int nc = 0; nc < 64; nc += 4) {
            float4 pv0 = pr[nc + 0], pv1 = pr[nc + 1], pv2 = pr[nc + 2], pv3 = pr[nc + 3];
#pragma unroll
            for (int li = 0; li < 8; li++) {
                const float4* fr = (const float4*)(fs + (size_t)(lg * 8 + li) * N_TOK);
                float4 f0 = fr[nc + 0], f1 = fr[nc + 1], f2 = fr[nc + 2], f3 = fr[nc + 3];
                float a = acc[li];
                a += f0.x * pv0.x + f0.y * pv0.y + f0.z * pv0.z + f0.w * pv0.w;
                a += f1.x * pv1.x + f1.y * pv1.y + f1.z * pv1.z + f1.w * pv1.w;
                a += f2.x * pv2.x + f2.y * pv2.y + f2.z * pv2.z + f2.w * pv2.w;
                a += f3.x * pv3.x + f3.y * pv3.y + f3.z * pv3.z + f3.w * pv3.w;
                acc[li] = a;
            }
        }
#pragma unroll
        for (int li = 0; li < 8; li++)
            vs[(half * 64 + lg * 8 + li) * 64 + m] = acc[li];
        __syncthreads();   // done with this half's fs before overwrite
    }

    // intra-norm over l per cluster m
    if (tid < 64) {
        float ss = 0.f;
        for (int l = 0; l < 128; l++) {
            float vv = vs[l * 64 + tid];
            ss += vv * vv;
        }
        inv[tid] = 1.f / fmaxf(sqrtf(ss), 1e-12f);
    }
    __syncthreads();

    // token L2 norm (threads 0-255)
    float tval = 0.f;
    if (tid < 256) tval = g_tg[(size_t)b * G_DIM + tid];
    float sst = tval * tval;
#pragma unroll
    for (int off = 16; off; off >>= 1) sst += __shfl_xor_sync(0xffffffffu, sst, off);
    if (lane == 0) red[w] = sst;
    __syncthreads();
    float ttot = 0.f;
#pragma unroll
    for (int i = 0; i < 8; i++) ttot += red[i];
    float tnorm = tval * (1.f / fmaxf(sqrtf(ttot), 1e-12f));
    __syncthreads();

    // final whole-vector norm
    float ssf = (tid < 256) ? tnorm * tnorm : 0.f;
    for (int i = tid; i < L_DIM * M_CL; i += TAIL_THREADS) {
        float vv = vs[i] * inv[i & 63];
        ssf += vv * vv;
    }
#pragma unroll
    for (int off = 16; off; off >>= 1) ssf += __shfl_xor_sync(0xffffffffu, ssf, off);
    if (lane == 0) red[w] = ssf;
    __syncthreads();
    float tot = 0.f;
#pragma unroll
    for (int i = 0; i < 16; i++) tot += red[i];
    float sc = 1.f / fmaxf(sqrtf(tot), 1e-12f);

    // write out
    float* O = out + (size_t)b * OUT_PER_B;
    if (tid < 256) O[tid] = tnorm * sc;
    for (int i = tid; i < L_DIM * M_CL; i += TAIL_THREADS)
        O[G_DIM + i] = vs[i] * inv[i & 63] * sc;
}

// ==========================================================================
// launch — 4 kernels
// ==========================================================================
extern "C" void kernel_launch(void* const* d_in, const int* in_sizes, int n_in,
                              void* d_out, int out_size)
{
    (void)in_sizes; (void)n_in; (void)out_size;
    const float* x    = (const float*)d_in[0];
    const float* t    = (const float*)d_in[1];
    const float* Wt1  = (const float*)d_in[2];
    const float* bt1  = (const float*)d_in[3];
    const float* Wt2  = (const float*)d_in[4];
    const float* bt2  = (const float*)d_in[5];
    const float* Wc1  = (const float*)d_in[6];
    const float* bc1  = (const float*)d_in[7];
    const float* Wc2  = (const float*)d_in[8];
    const float* bc2  = (const float*)d_in[9];
    const float* Ws1  = (const float*)d_in[10];
    const float* bs1  = (const float*)d_in[11];
    const float* Ws2  = (const float*)d_in[12];
    const float* bs2  = (const float*)d_in[13];
    const float* dust = (const float*)d_in[14];
    float* out = (float*)d_out;

    cudaFuncSetAttribute(k1_mma, cudaFuncAttributeMaxDynamicSharedMemorySize, GEMM_SMEM);
    cudaFuncSetAttribute(k2_mma, cudaFuncAttributeMaxDynamicSharedMemorySize, GEMM_SMEM);
    cudaFuncSetAttribute(k_tail, cudaFuncAttributeMaxDynamicSharedMemorySize, TAIL_SMEM);

    p_prep<<<XT_BLOCKS + PW_BLOCKS, 256>>>(x, Wc1, Ws1, Wc2, Ws2, Wt1, Wt2, t);  // idx 0
    k1_mma<<<dim3(2, 9, B_SZ), 256, GEMM_SMEM>>>(bc1, bs1, bt1);                  // idx 1
    k2_mma<<<dim3(2, 3, B_SZ), 256, GEMM_SMEM>>>(bc2, bs2, bt2);                  // idx 2
    k_tail<<<B_SZ, TAIL_THREADS, TAIL_SMEM>>>(dust, out);                         // idx 3 (ncu)
}